// round 6
// baseline (speedup 1.0000x reference)
#include <cuda_runtime.h>
#include <cuda_bf16.h>
#include <math.h>
#include <stdint.h>

// ---------------------------------------------------------------------------
// 2-layer LSTM, T=512, B=64, H=512, fp32 in/out. Persistent kernel, 128 CTAs
// x 512 threads. NEW in R5: GEMMs on tensor cores via mma.sync.m16n8k16.bf16
// with 3-term bf16 hi/lo split (Whi*Ahi + Whi*Alo + Wlo*Ahi, fp32 accum) for
// fp32-grade accuracy. Weights resident in smem as bf16 hi/lo, rows padded
// 1040B (ldmatrix conflict-free). Activations (x pre-split; h written as
// hi/lo bf16 at update) in [b][k] row-major = mma col-major B; staged via
// cp.async.cg double-buffered 32-k chunks, ldmatrix both operands.
// 16 warps = 2 K-teams x 8 N-tiles. 3-slot h rotation => 1 grid bar/step.
// ---------------------------------------------------------------------------

#define T_LEN 512
#define BSZ   64
#define HID   512
#define NCTA  128
#define NTHR  512

// smem byte layout
#define WMAT_BYTES  (16*1040)                 // one 16x512 bf16 mat, padded rows
#define W_OFF       0                         // 8 mats: [m(4)][part(2)]
#define AB_OFF      (8*WMAT_BYTES)            // 133120
#define PART_BYTES  5120                      // 64 rows x 80B
#define BUF_BYTES   (2*PART_BYTES)            // hi+lo
#define TEAM_BYTES  (2*BUF_BYTES)             // double buffer
#define GB_OFF      (AB_OFF + 2*TEAM_BYTES)   // 174080
#define GB_F        (GB_OFF/4)                // float index
#define BS_OFF      (GB_OFF + 2176*4)         // 182784
#define BS_F        (BS_OFF/4)
#define SMEM_BYTES  (BS_OFF + 128)            // 182912

// persistent scratch
__device__ __nv_bfloat16 g_xhi[(size_t)T_LEN*BSZ*HID];
__device__ __nv_bfloat16 g_xlo[(size_t)T_LEN*BSZ*HID];
__device__ __nv_bfloat16 g_h0hi[3][BSZ*HID], g_h0lo[3][BSZ*HID];
__device__ __nv_bfloat16 g_h1hi[3][BSZ*HID], g_h1lo[3][BSZ*HID];
__device__ unsigned g_cnt;    // returns to 0 after each barrier
__device__ unsigned g_gen;    // monotonic across launches (ok)

__device__ __forceinline__ float sigm(float x) { return 1.0f / (1.0f + expf(-x)); }

__device__ __forceinline__ void cp16s(uint32_t dst, const void* src) {
    asm volatile("cp.async.cg.shared.global [%0], [%1], 16;" :: "r"(dst), "l"(src));
}
__device__ __forceinline__ void ldsm_x4(uint32_t addr, uint32_t r[4]) {
    asm volatile("ldmatrix.sync.aligned.m8n8.x4.shared.b16 {%0,%1,%2,%3}, [%4];"
        : "=r"(r[0]), "=r"(r[1]), "=r"(r[2]), "=r"(r[3]) : "r"(addr));
}
__device__ __forceinline__ void ldsm_x2(uint32_t addr, uint32_t r[2]) {
    asm volatile("ldmatrix.sync.aligned.m8n8.x2.shared.b16 {%0,%1}, [%2];"
        : "=r"(r[0]), "=r"(r[1]) : "r"(addr));
}
__device__ __forceinline__ void mma16816(float d[4], const uint32_t a[4],
                                         const uint32_t b[2]) {
    asm volatile("mma.sync.aligned.m16n8k16.row.col.f32.bf16.bf16.f32 "
        "{%0,%1,%2,%3}, {%4,%5,%6,%7}, {%8,%9}, {%0,%1,%2,%3};"
        : "+f"(d[0]), "+f"(d[1]), "+f"(d[2]), "+f"(d[3])
        : "r"(a[0]), "r"(a[1]), "r"(a[2]), "r"(a[3]), "r"(b[0]), "r"(b[1]));
}

// Grid-wide barrier (proven since R1). All 128 CTAs co-resident.
__device__ __forceinline__ void grid_bar() {
    __threadfence();
    __syncthreads();
    if (threadIdx.x == 0) {
        volatile unsigned* vg = &g_gen;
        unsigned g = *vg;
        unsigned t = atomicAdd(&g_cnt, 1u);
        if (t == NCTA - 1) {
            atomicExch(&g_cnt, 0u);
            __threadfence();
            atomicAdd(&g_gen, 1u);
        } else {
            while (*vg == g) { }
        }
        __threadfence();
    }
    __syncthreads();
}

// Stage one 32-k chunk (hi+lo) of activations [64b][32k] into the team tile.
// Each of 256 team threads issues 2x cp16.
__device__ __forceinline__ void stage_chunk(
    uint32_t ab_base, int buf, const __nv_bfloat16* __restrict__ Ah,
    const __nv_bfloat16* __restrict__ Al, int k0, int j)
{
    int part = j >> 7, r2 = j & 127, b = r2 >> 1, seg = r2 & 1;
    const __nv_bfloat16* s = (part ? Al : Ah) + b * HID + k0 + seg * 16;
    uint32_t d = ab_base + buf * BUF_BYTES + part * PART_BYTES + b * 80 + seg * 32;
    cp16s(d, s);
    cp16s(d + 16, s + 8);
}

// One layer's GEMM: D[16c][64b] = Act_in . Wx^T + Act_rec . Wh^T via bf16
// 3-term mma. Team kt (warps kt*8..kt*8+7, named bar kt+1) covers
// k in [kt*256,(kt+1)*256). Warp nt owns batches nt*8..+7; accum d[4].
__device__ __forceinline__ void gemm_layer(
    uint32_t smb, int l,
    const __nv_bfloat16* __restrict__ A0h, const __nv_bfloat16* __restrict__ A0l,
    const __nv_bfloat16* __restrict__ A1h, const __nv_bfloat16* __restrict__ A1l,
    int kt, int j256, int nt, int lane, float d[4])
{
    d[0] = d[1] = d[2] = d[3] = 0.f;
    uint32_t ab_base = smb + AB_OFF + kt * TEAM_BYTES;

    int wrow = (lane & 7) + ((lane >> 3) & 1) * 8;
    uint32_t w_lane = (uint32_t)(wrow * 1040 + ((lane >> 4) & 1) * 16);
    uint32_t whi_in  = smb + W_OFF + (uint32_t)((l*2    ) * 2) * WMAT_BYTES + w_lane;
    uint32_t whi_rec = smb + W_OFF + (uint32_t)((l*2 + 1) * 2) * WMAT_BYTES + w_lane;
    int bl = lane & 15;
    uint32_t b_lane = (uint32_t)((nt * 8 + (bl & 7)) * 80 + (bl >> 3) * 16);

    const int kbase = kt * 256;
    stage_chunk(ab_base, 0, A0h, A0l, kbase,      j256);
    asm volatile("cp.async.commit_group;" ::: "memory");
    stage_chunk(ab_base, 1, A0h, A0l, kbase + 32, j256);
    asm volatile("cp.async.commit_group;" ::: "memory");

    #pragma unroll 1
    for (int i = 0; i < 16; i++) {
        if (i == 15) asm volatile("cp.async.wait_group 0;" ::: "memory");
        else         asm volatile("cp.async.wait_group 1;" ::: "memory");
        asm volatile("bar.sync %0, 256;" :: "r"(kt + 1) : "memory");

        int mat = i >> 3, ch = i & 7, buf = i & 1;
        uint32_t wb = mat ? whi_rec : whi_in;
        uint32_t kbyte = (uint32_t)((kbase + ch * 32) * 2);
        uint32_t bt = ab_base + buf * BUF_BYTES + b_lane;
        #pragma unroll
        for (int t16 = 0; t16 < 2; t16++) {
            uint32_t awh[4], awl[4], bh[2], blo[2];
            ldsm_x4(wb + kbyte + t16 * 32, awh);
            ldsm_x4(wb + WMAT_BYTES + kbyte + t16 * 32, awl);
            ldsm_x2(bt + t16 * 32, bh);
            ldsm_x2(bt + PART_BYTES + t16 * 32, blo);
            mma16816(d, awh, bh);    // Whi * Ahi
            mma16816(d, awh, blo);   // Whi * Alo
            mma16816(d, awl, bh);    // Wlo * Ahi
        }
        asm volatile("bar.sync %0, 256;" :: "r"(kt + 1) : "memory");
        if (i < 14) {
            int ni = i + 2;
            stage_chunk(ab_base, ni & 1, (ni >> 3) ? A1h : A0h,
                        (ni >> 3) ? A1l : A0l, kbase + (ni & 7) * 32, j256);
            asm volatile("cp.async.commit_group;" ::: "memory");
        }
    }
}

// D fragment -> gbuf[kt][c(16)][b(68 pad)] fp32
__device__ __forceinline__ void store_partials(float* smf, int kt, int nt,
                                               int lane, const float d[4])
{
    int g = lane >> 2, c2 = lane & 3;
    float* base = smf + GB_F + kt * 1088 + nt * 8 + 2 * c2;
    *(float2*)(base + g * 68)       = make_float2(d[0], d[1]);
    *(float2*)(base + (g + 8) * 68) = make_float2(d[2], d[3]);
}

__global__ void convert_x(const float* __restrict__ x) {
    size_t i = (size_t)blockIdx.x * blockDim.x + threadIdx.x;   // float4 idx
    float4 v = reinterpret_cast<const float4*>(x)[i];
    __nv_bfloat16 h0 = __float2bfloat16(v.x), h1 = __float2bfloat16(v.y),
                  h2 = __float2bfloat16(v.z), h3 = __float2bfloat16(v.w);
    __nv_bfloat16 l0 = __float2bfloat16(v.x - __bfloat162float(h0));
    __nv_bfloat16 l1 = __float2bfloat16(v.y - __bfloat162float(h1));
    __nv_bfloat16 l2 = __float2bfloat16(v.z - __bfloat162float(h2));
    __nv_bfloat16 l3 = __float2bfloat16(v.w - __bfloat162float(h3));
    __nv_bfloat162* ph = reinterpret_cast<__nv_bfloat162*>(g_xhi);
    __nv_bfloat162* pl = reinterpret_cast<__nv_bfloat162*>(g_xlo);
    ph[2*i] = __nv_bfloat162(h0, h1); ph[2*i + 1] = __nv_bfloat162(h2, h3);
    pl[2*i] = __nv_bfloat162(l0, l1); pl[2*i + 1] = __nv_bfloat162(l2, l3);
}

__global__ void __launch_bounds__(NTHR, 1) lstm_persistent(
    const float* __restrict__ Wxh,  // [2, 2048, 512]
    const float* __restrict__ Whh,  // [2, 2048, 512]
    const float* __restrict__ bxh,  // [2, 2048]
    const float* __restrict__ bhh,  // [2, 2048]
    float* __restrict__ out)        // [T*B*H] ++ hT[2,B,H] ++ cT[2,B,H]
{
    extern __shared__ float smf[];
    char* smc = (char*)smf;
    const uint32_t smb = (uint32_t)__cvta_generic_to_shared(smf);
    const int tid = threadIdx.x;
    const int bj  = blockIdx.x;

    // ---- prologue: weights -> smem bf16 hi/lo, padded rows; biases; h=0 ----
    for (int idx = tid; idx < 4 * 16 * 512; idx += NTHR) {
        int m = idx >> 13, rem = idx & 8191;
        int c = rem >> 9, k = rem & 511;
        int layer = m >> 1;
        const float* basep = (m & 1) ? Whh : Wxh;
        float w = basep[((size_t)layer * 2048 + (size_t)(c >> 2) * 512
                       + bj * 4 + (c & 3)) * 512 + k];
        __nv_bfloat16 hi = __float2bfloat16(w);
        __nv_bfloat16 lo = __float2bfloat16(w - __bfloat162float(hi));
        *(__nv_bfloat16*)(smc + (m*2    ) * WMAT_BYTES + c * 1040 + k * 2) = hi;
        *(__nv_bfloat16*)(smc + (m*2 + 1) * WMAT_BYTES + c * 1040 + k * 2) = lo;
    }
    if (tid < 32) {
        int l = tid >> 4, j = tid & 15;
        int n = (j >> 2) * 512 + bj * 4 + (j & 3);
        smf[BS_F + tid] = bxh[l * 2048 + n] + bhh[l * 2048 + n];
    }
    if (tid < 256) {      // zero h slot 2 (read at t=0): 128*256 = 32768
        int i = bj * 256 + tid;
        __nv_bfloat16 z = __float2bfloat16(0.f);
        g_h0hi[2][i] = z; g_h0lo[2][i] = z;
        g_h1hi[2][i] = z; g_h1lo[2][i] = z;
    }
    grid_bar();

    const int kt   = tid >> 8, j256 = tid & 255;       // team role
    const int nt   = (tid >> 5) & 7, lane = tid & 31;  // warp n-tile
    const int ub   = (tid & 255) >> 2, ucc = tid & 3;  // update role (tid<256)
    const int col  = bj * 4 + ucc;
    const int hidx = ub * HID + col;
    const float* bs = smf + BS_F;
    float c0r = 0.f, c1r = 0.f, h0last = 0.f, h1last = 0.f;
    float d[4];
    int rp = 2, wp = 0;

    for (int t = 0; t < T_LEN; t++) {
        const size_t xo = (size_t)t * (BSZ * HID);

        // ================= layer 0 =================
        gemm_layer(smb, 0, g_xhi + xo, g_xlo + xo, g_h0hi[rp], g_h0lo[rp],
                   kt, j256, nt, lane, d);
        __syncthreads();                 // prev update's gbuf reads done
        store_partials(smf, kt, nt, lane, d);
        __syncthreads();
        if (tid < 256) {
            float gate[4];
            #pragma unroll
            for (int g = 0; g < 4; g++) {
                const float* q = smf + GB_F + (g * 4 + ucc) * 68 + ub;
                gate[g] = q[0] + q[1088] + bs[g * 4 + ucc];
            }
            float ig = sigm(gate[0]), fg = sigm(gate[1]);
            float gg = tanhf(gate[2]), og = sigm(gate[3]);
            c0r = fg * c0r + ig * gg;
            h0last = og * tanhf(c0r);
            __nv_bfloat16 hh = __float2bfloat16(h0last);
            g_h0hi[wp][hidx] = hh;
            g_h0lo[wp][hidx] = __float2bfloat16(h0last - __bfloat162float(hh));
        }
        grid_bar();                      // the one barrier per step

        // ================= layer 1 =================
        gemm_layer(smb, 1, g_h0hi[wp], g_h0lo[wp], g_h1hi[rp], g_h1lo[rp],
                   kt, j256, nt, lane, d);
        __syncthreads();
        store_partials(smf, kt, nt, lane, d);
        __syncthreads();
        if (tid < 256) {
            float gate[4];
            #pragma unroll
            for (int g = 0; g < 4; g++) {
                const float* q = smf + GB_F + (g * 4 + ucc) * 68 + ub;
                gate[g] = q[0] + q[1088] + bs[16 + g * 4 + ucc];
            }
            float ig = sigm(gate[0]), fg = sigm(gate[1]);
            float gg = tanhf(gate[2]), og = sigm(gate[3]);
            c1r = fg * c1r + ig * gg;
            h1last = og * tanhf(c1r);
            __nv_bfloat16 hh = __float2bfloat16(h1last);
            g_h1hi[wp][hidx] = hh;
            g_h1lo[wp][hidx] = __float2bfloat16(h1last - __bfloat162float(hh));
            out[xo + hidx] = h1last;
        }
        // 3-slot rotation: next-step L0 reads stay safe without a 2nd bar
        rp = wp;
        wp = (wp == 2) ? 0 : wp + 1;
    }

    // ---- epilogue: (hT, cT) straight from registers ----
    if (tid < 256) {
        const size_t OFF = (size_t)T_LEN * BSZ * HID;
        out[OFF +         hidx] = h0last;
        out[OFF + 32768 + hidx] = h1last;
        out[OFF + 65536 + hidx] = c0r;
        out[OFF + 98304 + hidx] = c1r;
    }
}

extern "C" void kernel_launch(void* const* d_in, const int* in_sizes, int n_in,
                              void* d_out, int out_size) {
    const float* x   = (const float*)d_in[0];
    const float* Wxh = (const float*)d_in[1];
    const float* Whh = (const float*)d_in[2];
    const float* bxh = (const float*)d_in[3];
    const float* bhh = (const float*)d_in[4];
    float* out = (float*)d_out;

    convert_x<<<(T_LEN * BSZ * HID / 4) / 256, 256>>>(x);

    cudaFuncSetAttribute(lstm_persistent,
                         cudaFuncAttributeMaxDynamicSharedMemorySize, SMEM_BYTES);
    lstm_persistent<<<NCTA, NTHR, SMEM_BYTES>>>(Wxh, Whh, bxh, bhh, out);
}

// round 7
// speedup vs baseline: 1.2300x; 1.2300x over previous
#include <cuda_runtime.h>
#include <cuda_bf16.h>
#include <math.h>
#include <stdint.h>

// ---------------------------------------------------------------------------
// 2-layer LSTM, T=512, B=64, H=512, fp32 in/out. Persistent, 128 CTAs x 512.
// R7: weight mma-fragments live in REGISTERS (64 regs/thread, loaded once);
// no weight smem, no weight LDSM in the loop. 16 warps = 16 k-slices (32k);
// each warp does all 8 n-tiles for its slice, 3-term bf16 hi/lo mma
// (Whi*Ahi + Whi*Alo + Wlo*Ahi, fp32 accum). Activations staged as 4 chunks
// per layer (in/rec x batch-half, 64KB) into 2 ping-pong buffers, ONE
// __syncthreads per chunk. x chunk-0 pre-staged during previous update.
// 3-slot h rotation => 1 grid barrier/step. Cell state in registers.
// ---------------------------------------------------------------------------

#define T_LEN 512
#define BSZ   64
#define HID   512
#define NCTA  128
#define NTHR  512

// smem byte layout
#define PARTB   33280                 // 32 rows x 1040B (one part of a chunk)
#define CHUNKB  (2*PARTB)             // hi+lo = 66560
#define BUF(i)  ((uint32_t)(i)*CHUNKB)
#define GBO     (2*CHUNKB)            // 133120: partials [16 ks][16 c][68 pad]
#define GBF     (GBO/4)
#define BSO     (GBO + 16*16*68*4)    // 202752
#define BSF     (BSO/4)
#define SMEM_BYTES (BSO + 128)        // 202880

// persistent scratch
__device__ __nv_bfloat16 g_xhi[(size_t)T_LEN*BSZ*HID];
__device__ __nv_bfloat16 g_xlo[(size_t)T_LEN*BSZ*HID];
__device__ __nv_bfloat16 g_h0hi[3][BSZ*HID], g_h0lo[3][BSZ*HID];
__device__ __nv_bfloat16 g_h1hi[3][BSZ*HID], g_h1lo[3][BSZ*HID];
__device__ unsigned g_cnt;    // returns to 0 after each barrier
__device__ unsigned g_gen;    // monotonic across launches (ok)

__device__ __forceinline__ float sigm(float x) { return 1.0f / (1.0f + expf(-x)); }

__device__ __forceinline__ void cp16s(uint32_t dst, const void* src) {
    asm volatile("cp.async.cg.shared.global [%0], [%1], 16;" :: "r"(dst), "l"(src));
}
__device__ __forceinline__ void ldsm_x4(uint32_t addr, uint32_t r[4]) {
    asm volatile("ldmatrix.sync.aligned.m8n8.x4.shared.b16 {%0,%1,%2,%3}, [%4];"
        : "=r"(r[0]), "=r"(r[1]), "=r"(r[2]), "=r"(r[3]) : "r"(addr));
}
__device__ __forceinline__ void mma16816(float d[4], const uint32_t a[4],
                                         const uint32_t b[2]) {
    asm volatile("mma.sync.aligned.m16n8k16.row.col.f32.bf16.bf16.f32 "
        "{%0,%1,%2,%3}, {%4,%5,%6,%7}, {%8,%9}, {%0,%1,%2,%3};"
        : "+f"(d[0]), "+f"(d[1]), "+f"(d[2]), "+f"(d[3])
        : "r"(a[0]), "r"(a[1]), "r"(a[2]), "r"(a[3]), "r"(b[0]), "r"(b[1]));
}

// Grid-wide barrier (proven since R1). All 128 CTAs co-resident.
__device__ __forceinline__ void grid_bar() {
    __threadfence();
    __syncthreads();
    if (threadIdx.x == 0) {
        volatile unsigned* vg = &g_gen;
        unsigned g = *vg;
        unsigned t = atomicAdd(&g_cnt, 1u);
        if (t == NCTA - 1) {
            atomicExch(&g_cnt, 0u);
            __threadfence();
            atomicAdd(&g_gen, 1u);
        } else {
            while (*vg == g) { }
        }
        __threadfence();
    }
    __syncthreads();
}

// Stage one 32b x 512k (hi+lo) activation chunk into buffer bufo.
// All 512 threads, 8 x 16B each, one commit_group.
__device__ __forceinline__ void stage_chunk(uint32_t smb, uint32_t bufo,
    const __nv_bfloat16* __restrict__ Ah, const __nv_bfloat16* __restrict__ Al,
    int bh, int tid)
{
    int b0 = bh * 32;
    #pragma unroll
    for (int jj = 0; jj < 8; jj++) {
        int u = tid + jj * NTHR;
        int part = u >> 11, rem = u & 2047, b = rem >> 6, seg = rem & 63;
        const __nv_bfloat16* s = (part ? Al : Ah) + (size_t)(b0 + b) * HID + seg * 8;
        cp16s(smb + bufo + (uint32_t)(part * PARTB + b * 1040 + seg * 16), s);
    }
    asm volatile("cp.async.commit_group;" ::: "memory");
}

__global__ void convert_x(const float* __restrict__ x) {
    size_t i = (size_t)blockIdx.x * blockDim.x + threadIdx.x;   // float4 idx
    float4 v = reinterpret_cast<const float4*>(x)[i];
    __nv_bfloat16 h0 = __float2bfloat16(v.x), h1 = __float2bfloat16(v.y),
                  h2 = __float2bfloat16(v.z), h3 = __float2bfloat16(v.w);
    __nv_bfloat16 l0 = __float2bfloat16(v.x - __bfloat162float(h0));
    __nv_bfloat16 l1 = __float2bfloat16(v.y - __bfloat162float(h1));
    __nv_bfloat16 l2 = __float2bfloat16(v.z - __bfloat162float(h2));
    __nv_bfloat16 l3 = __float2bfloat16(v.w - __bfloat162float(h3));
    __nv_bfloat162* ph = reinterpret_cast<__nv_bfloat162*>(g_xhi);
    __nv_bfloat162* pl = reinterpret_cast<__nv_bfloat162*>(g_xlo);
    ph[2*i] = __nv_bfloat162(h0, h1); ph[2*i + 1] = __nv_bfloat162(h2, h3);
    pl[2*i] = __nv_bfloat162(l0, l1); pl[2*i + 1] = __nv_bfloat162(l2, l3);
}

__global__ void __launch_bounds__(NTHR, 1) lstm_persistent(
    const float* __restrict__ Wxh,  // [2, 2048, 512]
    const float* __restrict__ Whh,  // [2, 2048, 512]
    const float* __restrict__ bxh,  // [2, 2048]
    const float* __restrict__ bhh,  // [2, 2048]
    float* __restrict__ out)        // [T*B*H] ++ hT[2,B,H] ++ cT[2,B,H]
{
    extern __shared__ float smf[];
    char* smc = (char*)smf;
    const uint32_t smb = (uint32_t)__cvta_generic_to_shared(smf);
    const int tid = threadIdx.x;
    const int bj  = blockIdx.x;

    const int ks = tid >> 5, lane = tid & 31;
    // ldmatrix lane offsets (bytes)
    const uint32_t wloff = (uint32_t)(((lane & 7) + ((lane >> 3) & 1) * 8) * 1040
                                     + ((lane >> 4) & 1) * 16);
    // B addr combines buffer base later; fold smem base + k-slice in
    const uint32_t bbase = smb + (uint32_t)((((lane >> 4) & 1) * 8 + (lane & 7)) * 1040
                                 + ((lane >> 3) & 1) * 16 + ks * 64);

    uint32_t wf[2][2][2][2][4];   // [layer][mat][part][kb][4] weight frags

    // ---- prologue: weights -> bf16 hi/lo tiles in buf area -> reg frags ----
    for (int l = 0; l < 2; l++) {
        for (int idx = tid; idx < 16384; idx += NTHR) {
            int m = idx >> 13, rem = idx & 8191, c = rem >> 9, k = rem & 511;
            const float* bp = m ? Whh : Wxh;
            float w = bp[((size_t)l * 2048 + (size_t)(c >> 2) * 512
                        + bj * 4 + (c & 3)) * 512 + k];
            __nv_bfloat16 hi = __float2bfloat16(w);
            __nv_bfloat16 lo = __float2bfloat16(w - __bfloat162float(hi));
            *(__nv_bfloat16*)(smc + (m * 2 + 0) * 16640 + c * 1040 + k * 2) = hi;
            *(__nv_bfloat16*)(smc + (m * 2 + 1) * 16640 + c * 1040 + k * 2) = lo;
        }
        __syncthreads();
        #pragma unroll
        for (int m = 0; m < 2; m++)
            #pragma unroll
            for (int p = 0; p < 2; p++)
                #pragma unroll
                for (int kb = 0; kb < 2; kb++)
                    ldsm_x4(smb + (uint32_t)((m * 2 + p) * 16640 + kb * 32 + ks * 64)
                            + wloff, wf[l][m][p][kb]);
        __syncthreads();
    }
    if (tid < 32) {
        int l = tid >> 4, j = tid & 15;
        int n = (j >> 2) * 512 + bj * 4 + (j & 3);
        smf[BSF + tid] = bxh[l * 2048 + n] + bhh[l * 2048 + n];
    }
    if (tid < 256) {      // zero h slot 2 (read at t=0): 128*256 = 32768
        int i = bj * 256 + tid;
        __nv_bfloat16 z = __float2bfloat16(0.f);
        g_h0hi[2][i] = z; g_h0lo[2][i] = z;
        g_h1hi[2][i] = z; g_h1lo[2][i] = z;
    }
    // pre-stage t=0, L0 chunk0 (x, batch-half 0)
    stage_chunk(smb, BUF(0), g_xhi, g_xlo, 0, tid);
    grid_bar();

    const int ub = (tid & 255) >> 2, ucc = tid & 3;   // update role (tid<256)
    const int col = bj * 4 + ucc;
    const int hidx = ub * HID + col;
    float c0r = 0.f, c1r = 0.f, h0last = 0.f, h1last = 0.f;
    float d[8][4];
    int rp = 2, wp = 0;

    for (int t = 0; t < T_LEN; t++) {
        const size_t xo = (size_t)t * (BSZ * HID);

        #pragma unroll
        for (int l = 0; l < 2; l++) {
            const __nv_bfloat16 *Inh, *Inl, *Reh, *Rel;
            if (l == 0) { Inh = g_xhi + xo;  Inl = g_xlo + xo;
                          Reh = g_h0hi[rp];  Rel = g_h0lo[rp]; }
            else        { Inh = g_h0hi[wp];  Inl = g_h0lo[wp];
                          Reh = g_h1hi[rp];  Rel = g_h1lo[rp]; }

            #pragma unroll
            for (int nt = 0; nt < 8; nt++)
                d[nt][0] = d[nt][1] = d[nt][2] = d[nt][3] = 0.f;

            #pragma unroll
            for (int i = 0; i < 4; i++) {
                asm volatile("cp.async.wait_group 0;" ::: "memory");
                __syncthreads();     // chunk i visible; buf (i+1)&1 free
                if (i < 3) {
                    int ni = i + 1;
                    stage_chunk(smb, BUF(ni & 1), (ni >> 1) ? Reh : Inh,
                                (ni >> 1) ? Rel : Inl, ni & 1, tid);
                }
                const int m = i >> 1;        // 0=in, 1=rec
                #pragma unroll
                for (int pair = 0; pair < 2; pair++) {
                    #pragma unroll
                    for (int kb = 0; kb < 2; kb++) {
                        uint32_t bb = bbase + BUF(i & 1)
                                    + (uint32_t)(pair * 16640 + kb * 32);
                        uint32_t bh4[4], bl4[4];
                        ldsm_x4(bb, bh4);
                        ldsm_x4(bb + PARTB, bl4);
                        const int nt = (i & 1) * 4 + pair * 2;
                        mma16816(d[nt],     wf[l][m][0][kb], bh4);
                        mma16816(d[nt],     wf[l][m][0][kb], bl4);
                        mma16816(d[nt],     wf[l][m][1][kb], bh4);
                        mma16816(d[nt + 1], wf[l][m][0][kb], bh4 + 2);
                        mma16816(d[nt + 1], wf[l][m][0][kb], bl4 + 2);
                        mma16816(d[nt + 1], wf[l][m][1][kb], bh4 + 2);
                    }
                }
            }

            // store k-slice partials: gbuf[ks][c16][68]
            {
                float* gb0 = smf + GBF + ks * 1088 + (lane >> 2) * 68
                           + 2 * (lane & 3);
                #pragma unroll
                for (int nt = 0; nt < 8; nt++) {
                    *(float2*)(gb0 + nt * 8)          = make_float2(d[nt][0], d[nt][1]);
                    *(float2*)(gb0 + 8 * 68 + nt * 8) = make_float2(d[nt][2], d[nt][3]);
                }
            }
            __syncthreads();

            if (l == 1) {   // pre-stage next step's x chunk0 (overlaps update)
                size_t xo2 = (size_t)((t + 1 < T_LEN) ? t + 1 : t) * (BSZ * HID);
                stage_chunk(smb, BUF(0), g_xhi + xo2, g_xlo + xo2, 0, tid);
            }

            if (tid < 256) {
                float gate[4];
                #pragma unroll
                for (int g = 0; g < 4; g++) {
                    const float* q = smf + GBF + (g * 4 + ucc) * 68 + ub;
                    float s = smf[BSF + l * 16 + g * 4 + ucc];
                    #pragma unroll
                    for (int sI = 0; sI < 16; sI++) s += q[sI * 1088];
                    gate[g] = s;
                }
                float ig = sigm(gate[0]), fg = sigm(gate[1]);
                float gg = tanhf(gate[2]), og = sigm(gate[3]);
                if (l == 0) {
                    c0r = fg * c0r + ig * gg;
                    h0last = og * tanhf(c0r);
                    __nv_bfloat16 hh = __float2bfloat16(h0last);
                    g_h0hi[wp][hidx] = hh;
                    g_h0lo[wp][hidx] = __float2bfloat16(h0last - __bfloat162float(hh));
                } else {
                    c1r = fg * c1r + ig * gg;
                    h1last = og * tanhf(c1r);
                    __nv_bfloat16 hh = __float2bfloat16(h1last);
                    g_h1hi[wp][hidx] = hh;
                    g_h1lo[wp][hidx] = __float2bfloat16(h1last - __bfloat162float(hh));
                    out[xo + hidx] = h1last;
                }
            }

            if (l == 0) {
                grid_bar();          // the one barrier per step
                // pre-stage L1 chunk0 (new h0, batch-half 0)
                stage_chunk(smb, BUF(0), g_h0hi[wp], g_h0lo[wp], 0, tid);
            }
        }
        rp = wp;
        wp = (wp == 2) ? 0 : wp + 1;
    }

    asm volatile("cp.async.wait_group 0;" ::: "memory");

    // ---- epilogue: (hT, cT) straight from registers ----
    if (tid < 256) {
        const size_t OFF = (size_t)T_LEN * BSZ * HID;
        out[OFF +         hidx] = h0last;
        out[OFF + 32768 + hidx] = h1last;
        out[OFF + 65536 + hidx] = c0r;
        out[OFF + 98304 + hidx] = c1r;
    }
}

extern "C" void kernel_launch(void* const* d_in, const int* in_sizes, int n_in,
                              void* d_out, int out_size) {
    const float* x   = (const float*)d_in[0];
    const float* Wxh = (const float*)d_in[1];
    const float* Whh = (const float*)d_in[2];
    const float* bxh = (const float*)d_in[3];
    const float* bhh = (const float*)d_in[4];
    float* out = (float*)d_out;

    convert_x<<<(T_LEN * BSZ * HID / 4) / 256, 256>>>(x);

    cudaFuncSetAttribute(lstm_persistent,
                         cudaFuncAttributeMaxDynamicSharedMemorySize, SMEM_BYTES);
    lstm_persistent<<<NCTA, NTHR, SMEM_BYTES>>>(Wxh, Whh, bxh, bhh, out);
}

// round 8
// speedup vs baseline: 1.5541x; 1.2635x over previous
#include <cuda_runtime.h>
#include <cuda_bf16.h>
#include <math.h>
#include <stdint.h>

// ---------------------------------------------------------------------------
// 2-layer LSTM, T=512, B=64, H=512, fp32 in/out. Persistent, 128 CTAs x 512.
// R8: per grid-bar interval t, compute L1(t) AND L0(t+1) together from 6
// staged chunks: x(t+1) x2, h0(t) x2 (shared by both GEMMs!), h1(t-1) x2.
// Warps 0-7 = L1 GEMM, warps 8-15 = L0' GEMM (64k-slices, weight frags in
// regs, one 32-reg accumulator set each). bf16 hi/lo 3-term mma. 2-buffer
// cp.async pipeline; next-x chunk pre-staged before the grid barrier.
// Both updates batched at interval end. 3-slot h rotation, 1 bar/step.
// ---------------------------------------------------------------------------

#define T_LEN 512
#define BSZ   64
#define HID   512
#define NCTA  128
#define NTHR  512

// smem byte layout
#define PARTB   33280u                 // 32 rows x 1040B (hi or lo part)
#define CHUNKB  (2u*PARTB)             // 66560
#define BUF(i)  ((uint32_t)(i)*CHUNKB) // 2 buffers
#define GB0O    (2u*CHUNKB)            // 133120: L0 partials [8ks][16c][68]
#define GB1O    (GB0O + 34816u)        // 167936: L1 partials
#define GB0F    (GB0O/4u)
#define GB1F    (GB1O/4u)
#define BSO     (GB1O + 34816u)        // 202752
#define BSF     (BSO/4u)
#define SMEM_BYTES (BSO + 128u)        // 202880

// persistent scratch
__device__ __nv_bfloat16 g_xhi[(size_t)T_LEN*BSZ*HID];
__device__ __nv_bfloat16 g_xlo[(size_t)T_LEN*BSZ*HID];
__device__ __nv_bfloat16 g_h0hi[3][BSZ*HID], g_h0lo[3][BSZ*HID];
__device__ __nv_bfloat16 g_h1hi[3][BSZ*HID], g_h1lo[3][BSZ*HID];
__device__ unsigned g_cnt;
__device__ unsigned g_gen;

__device__ __forceinline__ float sigm(float x) { return 1.0f / (1.0f + expf(-x)); }

__device__ __forceinline__ void cp16s(uint32_t dst, const void* src) {
    asm volatile("cp.async.cg.shared.global [%0], [%1], 16;" :: "r"(dst), "l"(src));
}
__device__ __forceinline__ void ldsm_x4(uint32_t addr, uint32_t r[4]) {
    asm volatile("ldmatrix.sync.aligned.m8n8.x4.shared.b16 {%0,%1,%2,%3}, [%4];"
        : "=r"(r[0]), "=r"(r[1]), "=r"(r[2]), "=r"(r[3]) : "r"(addr));
}
__device__ __forceinline__ void mma16816(float d[4], const uint32_t a[4],
                                         const uint32_t b[2]) {
    asm volatile("mma.sync.aligned.m16n8k16.row.col.f32.bf16.bf16.f32 "
        "{%0,%1,%2,%3}, {%4,%5,%6,%7}, {%8,%9}, {%0,%1,%2,%3};"
        : "+f"(d[0]), "+f"(d[1]), "+f"(d[2]), "+f"(d[3])
        : "r"(a[0]), "r"(a[1]), "r"(a[2]), "r"(a[3]), "r"(b[0]), "r"(b[1]));
}
#define CPWAIT(n) asm volatile("cp.async.wait_group %0;" :: "n"(n) : "memory")
#define CPCOMMIT() asm volatile("cp.async.commit_group;" ::: "memory")

// Grid-wide barrier (proven since R1). All 128 CTAs co-resident.
__device__ __forceinline__ void grid_bar() {
    __threadfence();
    __syncthreads();
    if (threadIdx.x == 0) {
        volatile unsigned* vg = &g_gen;
        unsigned g = *vg;
        unsigned t = atomicAdd(&g_cnt, 1u);
        if (t == NCTA - 1) {
            atomicExch(&g_cnt, 0u);
            __threadfence();
            atomicAdd(&g_gen, 1u);
        } else {
            while (*vg == g) { }
        }
        __threadfence();
    }
    __syncthreads();
}

// Stage one 32-batch x 512-k (hi+lo) chunk into buffer. All 512 threads.
__device__ __forceinline__ void stage_chunk(uint32_t smb, uint32_t bufo,
    const __nv_bfloat16* __restrict__ Ah, const __nv_bfloat16* __restrict__ Al,
    int half, int tid)
{
    int b0 = half * 32;
    #pragma unroll
    for (int jj = 0; jj < 8; jj++) {
        int u = tid + jj * NTHR;
        int part = u >> 11, rem = u & 2047, b = rem >> 6, seg = rem & 63;
        const __nv_bfloat16* s = (part ? Al : Ah) + (size_t)(b0 + b) * HID + seg * 8;
        cp16s(smb + bufo + (uint32_t)(part * PARTB + b * 1040 + seg * 16), s);
    }
    CPCOMMIT();
}

// One chunk's MMA work for this warp: 64k-slice, 3-term hi/lo.
// wfm[p][kb][4]: weight frags for the selected mat. half: batch half (n base).
__device__ __forceinline__ void chunk_mma(uint32_t smb, uint32_t bufo, int half,
    const uint32_t wfm[2][4][4], uint32_t blane, int myks, float d[8][4])
{
    #pragma unroll
    for (int pair = 0; pair < 2; pair++) {
        #pragma unroll
        for (int kb = 0; kb < 4; kb++) {
            uint32_t addr = smb + bufo + (uint32_t)(pair * 16640) + blane
                          + (uint32_t)(myks * 128 + kb * 32);
            uint32_t bh4[4], bl4[4];
            ldsm_x4(addr, bh4);
            ldsm_x4(addr + PARTB, bl4);
            int nt = half * 4 + pair * 2;
            mma16816(d[nt],     wfm[0][kb], bh4);
            mma16816(d[nt],     wfm[0][kb], bl4);
            mma16816(d[nt],     wfm[1][kb], bh4);
            mma16816(d[nt + 1], wfm[0][kb], bh4 + 2);
            mma16816(d[nt + 1], wfm[0][kb], bl4 + 2);
            mma16816(d[nt + 1], wfm[1][kb], bh4 + 2);
        }
    }
}

__device__ __forceinline__ void store_partials(float* smf, uint32_t gbF,
    int myks, int lane, const float d[8][4])
{
    float* gb0 = smf + gbF + myks * 1088 + (lane >> 2) * 68 + 2 * (lane & 3);
    #pragma unroll
    for (int nt = 0; nt < 8; nt++) {
        *(float2*)(gb0 + nt * 8)          = make_float2(d[nt][0], d[nt][1]);
        *(float2*)(gb0 + 8 * 68 + nt * 8) = make_float2(d[nt][2], d[nt][3]);
    }
}

__global__ void convert_x(const float* __restrict__ x) {
    size_t i = (size_t)blockIdx.x * blockDim.x + threadIdx.x;   // float4 idx
    float4 v = reinterpret_cast<const float4*>(x)[i];
    __nv_bfloat16 h0 = __float2bfloat16(v.x), h1 = __float2bfloat16(v.y),
                  h2 = __float2bfloat16(v.z), h3 = __float2bfloat16(v.w);
    __nv_bfloat16 l0 = __float2bfloat16(v.x - __bfloat162float(h0));
    __nv_bfloat16 l1 = __float2bfloat16(v.y - __bfloat162float(h1));
    __nv_bfloat16 l2 = __float2bfloat16(v.z - __bfloat162float(h2));
    __nv_bfloat16 l3 = __float2bfloat16(v.w - __bfloat162float(h3));
    __nv_bfloat162* ph = reinterpret_cast<__nv_bfloat162*>(g_xhi);
    __nv_bfloat162* pl = reinterpret_cast<__nv_bfloat162*>(g_xlo);
    ph[2*i] = __nv_bfloat162(h0, h1); ph[2*i + 1] = __nv_bfloat162(h2, h3);
    pl[2*i] = __nv_bfloat162(l0, l1); pl[2*i + 1] = __nv_bfloat162(l2, l3);
}

__global__ void __launch_bounds__(NTHR, 1) lstm_persistent(
    const float* __restrict__ Wxh,  // [2, 2048, 512]
    const float* __restrict__ Whh,  // [2, 2048, 512]
    const float* __restrict__ bxh,  // [2, 2048]
    const float* __restrict__ bhh,  // [2, 2048]
    float* __restrict__ out)        // [T*B*H] ++ hT[2,B,H] ++ cT[2,B,H]
{
    extern __shared__ float smf[];
    char* smc = (char*)smf;
    const uint32_t smb = (uint32_t)__cvta_generic_to_shared(smf);
    const int tid = threadIdx.x;
    const int bj  = blockIdx.x;

    const int wid = tid >> 5, lane = tid & 31;
    const bool isL1 = (wid < 8);
    const int myks = isL1 ? wid : wid - 8;        // 64k slice index
    const int glayer = isL1 ? 1 : 0;

    const uint32_t wloff = (uint32_t)(((lane & 7) + ((lane >> 3) & 1) * 8) * 1040
                                     + ((lane >> 4) & 1) * 16);
    const uint32_t blane = (uint32_t)((((lane >> 4) & 1) * 8 + (lane & 7)) * 1040
                                     + ((lane >> 3) & 1) * 16);

    uint32_t wf[2][2][4][4];   // [mat: x/h][part: hi/lo][kb][4]

    // ---- prologue A: weights -> bf16 hi/lo tiles in smem -> reg frags ----
    for (int l = 0; l < 2; l++) {
        for (int idx = tid; idx < 16384; idx += NTHR) {
            int m = idx >> 13, rem = idx & 8191, c = rem >> 9, k = rem & 511;
            const float* bp = m ? Whh : Wxh;
            float w = bp[((size_t)l * 2048 + (size_t)(c >> 2) * 512
                        + bj * 4 + (c & 3)) * 512 + k];
            __nv_bfloat16 hi = __float2bfloat16(w);
            __nv_bfloat16 lo = __float2bfloat16(w - __bfloat162float(hi));
            *(__nv_bfloat16*)(smc + (m * 2 + 0) * 16640 + c * 1040 + k * 2) = hi;
            *(__nv_bfloat16*)(smc + (m * 2 + 1) * 16640 + c * 1040 + k * 2) = lo;
        }
        __syncthreads();
        if (glayer == l) {
            #pragma unroll
            for (int m = 0; m < 2; m++)
                #pragma unroll
                for (int p = 0; p < 2; p++)
                    #pragma unroll
                    for (int kb = 0; kb < 4; kb++)
                        ldsm_x4(smb + (uint32_t)((m * 2 + p) * 16640)
                                + wloff + (uint32_t)((myks * 64 + kb * 16) * 2),
                                wf[m][p][kb]);
        }
        __syncthreads();
    }
    if (tid < 32) {
        int l = tid >> 4, j = tid & 15;
        int n = (j >> 2) * 512 + bj * 4 + (j & 3);
        smf[BSF + tid] = bxh[l * 2048 + n] + bhh[l * 2048 + n];
    }
    if (tid < 256) {      // zero h1 slot 2 (read at t=0)
        int i = bj * 256 + tid;
        __nv_bfloat16 z = __float2bfloat16(0.f);
        g_h1hi[2][i] = z; g_h1lo[2][i] = z;
    }

    const int ub = tid >> 2, ucc = tid & 3;       // update role (tid<256)
    const int col = bj * 4 + ucc;
    const int hidx = ub * HID + col;
    float c0r = 0.f, c1r = 0.f, h0last = 0.f, h1last = 0.f;
    float d[8][4];

    // ---- prologue B: interval -1 => L0(0) gates = x(0).Wx0 + b ----
    {
        #pragma unroll
        for (int nt = 0; nt < 8; nt++)
            d[nt][0] = d[nt][1] = d[nt][2] = d[nt][3] = 0.f;
        stage_chunk(smb, BUF(0), g_xhi, g_xlo, 0, tid);
        stage_chunk(smb, BUF(1), g_xhi, g_xlo, 1, tid);
        CPWAIT(1); __syncthreads();
        if (!isL1) chunk_mma(smb, BUF(0), 0, wf[0], blane, myks, d);
        CPWAIT(0); __syncthreads();
        if (!isL1) {
            chunk_mma(smb, BUF(1), 1, wf[0], blane, myks, d);
            store_partials(smf, GB0F, myks, lane, d);
        }
        __syncthreads();
        if (tid < 256) {
            float gate[4];
            #pragma unroll
            for (int g = 0; g < 4; g++) {
                const float* q = smf + GB0F + (g * 4 + ucc) * 68 + ub;
                float s = smf[BSF + g * 4 + ucc];
                #pragma unroll
                for (int sI = 0; sI < 8; sI++) s += q[sI * 1088];
                gate[g] = s;
            }
            float ig = sigm(gate[0]), fg = sigm(gate[1]);
            float gg = tanhf(gate[2]), og = sigm(gate[3]);
            c0r = fg * c0r + ig * gg;
            h0last = og * tanhf(c0r);
            __nv_bfloat16 hh = __float2bfloat16(h0last);
            g_h0hi[0][hidx] = hh;
            g_h0lo[0][hidx] = __float2bfloat16(h0last - __bfloat162float(hh));
        }
        // pre-stage x(1)_half0 into buf0 (hides behind the grid bar)
        stage_chunk(smb, BUF(0), g_xhi + (size_t)BSZ * HID,
                    g_xlo + (size_t)BSZ * HID, 0, tid);
        grid_bar();
    }

    // ---- main loop: interval t computes L1(t) + L0(t+1) ----
    for (int t = 0; t < T_LEN; t++) {
        const int s_h0r = t % 3;              // h0(t) read slot
        const int s_h1r = (t + 2) % 3;        // h1(t-1) read slot
        const int s_h0w = (t + 1) % 3;        // h0(t+1) write slot
        const int s_h1w = t % 3;              // h1(t) write slot
        const size_t xo1 = (size_t)((t + 1 < T_LEN) ? t + 1 : T_LEN - 1) * (BSZ * HID);
        const size_t xo2 = (size_t)((t + 2 < T_LEN) ? t + 2 : T_LEN - 1) * (BSZ * HID);

        #pragma unroll
        for (int nt = 0; nt < 8; nt++)
            d[nt][0] = d[nt][1] = d[nt][2] = d[nt][3] = 0.f;

        // chunk 0: x(t+1)_0 (pre-staged, buf0). L0': in-mma (Wx0)
        CPWAIT(0); __syncthreads();
        stage_chunk(smb, BUF(1), g_h0hi[s_h0r], g_h0lo[s_h0r], 0, tid);
        if (!isL1) chunk_mma(smb, BUF(0), 0, wf[0], blane, myks, d);

        // chunk 1: h0_0 (buf1). L1: in (Wx1); L0': rec (Wh0)
        CPWAIT(0); __syncthreads();
        stage_chunk(smb, BUF(0), g_h0hi[s_h0r], g_h0lo[s_h0r], 1, tid);
        if (isL1) chunk_mma(smb, BUF(1), 0, wf[0], blane, myks, d);
        else      chunk_mma(smb, BUF(1), 0, wf[1], blane, myks, d);

        // chunk 2: h0_1 (buf0)
        CPWAIT(0); __syncthreads();
        stage_chunk(smb, BUF(1), g_h1hi[s_h1r], g_h1lo[s_h1r], 0, tid);
        if (isL1) chunk_mma(smb, BUF(0), 1, wf[0], blane, myks, d);
        else      chunk_mma(smb, BUF(0), 1, wf[1], blane, myks, d);

        // chunk 3: h1_0 (buf1). L1: rec (Wh1)
        CPWAIT(0); __syncthreads();
        stage_chunk(smb, BUF(0), g_h1hi[s_h1r], g_h1lo[s_h1r], 1, tid);
        if (isL1) chunk_mma(smb, BUF(1), 0, wf[1], blane, myks, d);

        // chunk 4: h1_1 (buf0). L1 done -> store partials
        CPWAIT(0); __syncthreads();
        stage_chunk(smb, BUF(1), g_xhi + xo1, g_xlo + xo1, 1, tid);
        if (isL1) {
            chunk_mma(smb, BUF(0), 1, wf[1], blane, myks, d);
            store_partials(smf, GB1F, myks, lane, d);
        }

        // chunk 5: x(t+1)_1 (buf1). L0' done -> store partials
        CPWAIT(0); __syncthreads();
        stage_chunk(smb, BUF(0), g_xhi + xo2, g_xlo + xo2, 0, tid);  // next x_0
        if (!isL1) {
            chunk_mma(smb, BUF(1), 1, wf[0], blane, myks, d);
            store_partials(smf, GB0F, myks, lane, d);
        }
        __syncthreads();

        // ---- batched updates (tid < 256) ----
        if (tid < 256) {
            float g1[4], g0[4];
            #pragma unroll
            for (int g = 0; g < 4; g++) {
                const float* q1 = smf + GB1F + (g * 4 + ucc) * 68 + ub;
                const float* q0 = smf + GB0F + (g * 4 + ucc) * 68 + ub;
                float s1 = smf[BSF + 16 + g * 4 + ucc];
                float s0 = smf[BSF +      g * 4 + ucc];
                #pragma unroll
                for (int sI = 0; sI < 8; sI++) { s1 += q1[sI * 1088];
                                                 s0 += q0[sI * 1088]; }
                g1[g] = s1; g0[g] = s0;
            }
            {
                float ig = sigm(g1[0]), fg = sigm(g1[1]);
                float gg = tanhf(g1[2]), og = sigm(g1[3]);
                c1r = fg * c1r + ig * gg;
                h1last = og * tanhf(c1r);
                __nv_bfloat16 hh = __float2bfloat16(h1last);
                g_h1hi[s_h1w][hidx] = hh;
                g_h1lo[s_h1w][hidx] = __float2bfloat16(h1last - __bfloat162float(hh));
                out[(size_t)t * (BSZ * HID) + hidx] = h1last;
            }
            if (t < T_LEN - 1) {
                float ig = sigm(g0[0]), fg = sigm(g0[1]);
                float gg = tanhf(g0[2]), og = sigm(g0[3]);
                c0r = fg * c0r + ig * gg;
                h0last = og * tanhf(c0r);
                __nv_bfloat16 hh = __float2bfloat16(h0last);
                g_h0hi[s_h0w][hidx] = hh;
                g_h0lo[s_h0w][hidx] = __float2bfloat16(h0last - __bfloat162float(hh));
            }
        }
        grid_bar();
    }
    CPWAIT(0);

    // ---- epilogue: (hT, cT) straight from registers ----
    if (tid < 256) {
        const size_t OFF = (size_t)T_LEN * BSZ * HID;
        out[OFF +         hidx] = h0last;
        out[OFF + 32768 + hidx] = h1last;
        out[OFF + 65536 + hidx] = c0r;
        out[OFF + 98304 + hidx] = c1r;
    }
}

extern "C" void kernel_launch(void* const* d_in, const int* in_sizes, int n_in,
                              void* d_out, int out_size) {
    const float* x   = (const float*)d_in[0];
    const float* Wxh = (const float*)d_in[1];
    const float* Whh = (const float*)d_in[2];
    const float* bxh = (const float*)d_in[3];
    const float* bhh = (const float*)d_in[4];
    float* out = (float*)d_out;

    convert_x<<<(T_LEN * BSZ * HID / 4) / 256, 256>>>(x);

    cudaFuncSetAttribute(lstm_persistent,
                         cudaFuncAttributeMaxDynamicSharedMemorySize, SMEM_BYTES);
    lstm_persistent<<<NCTA, NTHR, SMEM_BYTES>>>(Wxh, Whh, bxh, bhh, out);
}

// round 9
// speedup vs baseline: 2.1356x; 1.3742x over previous
#include <cuda_runtime.h>
#include <cuda_fp16.h>
#include <math.h>
#include <stdint.h>

// ---------------------------------------------------------------------------
// 2-layer LSTM, T=512, B=64, H=512, fp32 in/out. Persistent, 128 CTAs x 512.
// R9: two DECOUPLED warp-groups run concurrently per grid-bar interval t:
//   group A (warps 0-7):  L1(t)   gates = h0(t).Wx1 + h1(t-1).Wh1
//   group B (warps 8-15): L0(t+1) gates = x(t+1).Wx0 + h0(t).Wh0
// Each group: own 2-buffer ring (33KB fp16 chunks), own named barrier,
// 4 chunk-phases, weight frags (fp16 hi/lo, x256 prescale) in registers,
// 2-term mma m16n8k16.f16 (Whi*A + Wlo*A), fp32 accum, gates /256 at update.
// Groups meet only at one __syncthreads + the grid barrier. B prestages
// x chunks during A's update. 3-slot h rotation, 1 grid bar/step.
// ---------------------------------------------------------------------------

#define T_LEN 512
#define BSZ   64
#define HID   512
#define NCTA  128
#define NTHR  512

// smem byte layout
#define CHUNKB  33280u                    // 32 rows x 1040B (fp16, 512k + pad)
#define BUFA(i) ((uint32_t)(i)*CHUNKB)    // group A ring
#define BUFB(i) (2u*CHUNKB + (uint32_t)(i)*CHUNKB)
#define GB0O    (4u*CHUNKB)               // 133120: L0' partials [8ks][16c][68]
#define GB1O    (GB0O + 34816u)           // 167936: L1 partials
#define GB0F    (GB0O/4u)
#define GB1F    (GB1O/4u)
#define BSO     (GB1O + 34816u)           // 202752
#define BSF     (BSO/4u)
#define SMEM_BYTES (BSO + 128u)           // 202880

#define SCL 0.00390625f                   // 1/256 gate rescale

// persistent scratch (fp16 activations)
__device__ __half g_xh[(size_t)T_LEN*BSZ*HID];
__device__ __half g_h0h[3][BSZ*HID];
__device__ __half g_h1h[3][BSZ*HID];
__device__ unsigned g_cnt;
__device__ unsigned g_gen;

__device__ __forceinline__ float sigm(float x) { return 1.0f / (1.0f + expf(-x)); }

__device__ __forceinline__ void cp16s(uint32_t dst, const void* src) {
    asm volatile("cp.async.cg.shared.global [%0], [%1], 16;" :: "r"(dst), "l"(src));
}
__device__ __forceinline__ void ldsm_x4(uint32_t addr, uint32_t r[4]) {
    asm volatile("ldmatrix.sync.aligned.m8n8.x4.shared.b16 {%0,%1,%2,%3}, [%4];"
        : "=r"(r[0]), "=r"(r[1]), "=r"(r[2]), "=r"(r[3]) : "r"(addr));
}
__device__ __forceinline__ void mma16816(float d[4], const uint32_t a[4],
                                         const uint32_t b[2]) {
    asm volatile("mma.sync.aligned.m16n8k16.row.col.f32.f16.f16.f32 "
        "{%0,%1,%2,%3}, {%4,%5,%6,%7}, {%8,%9}, {%0,%1,%2,%3};"
        : "+f"(d[0]), "+f"(d[1]), "+f"(d[2]), "+f"(d[3])
        : "r"(a[0]), "r"(a[1]), "r"(a[2]), "r"(a[3]), "r"(b[0]), "r"(b[1]));
}
#define CPWAIT(n)  asm volatile("cp.async.wait_group %0;" :: "n"(n) : "memory")
#define CPCOMMIT() asm volatile("cp.async.commit_group;" ::: "memory")

__device__ __forceinline__ void barg(int id) {
    asm volatile("bar.sync %0, 256;" :: "r"(id) : "memory");
}

// Grid-wide barrier (proven since R1). All 128 CTAs co-resident.
__device__ __forceinline__ void grid_bar() {
    __threadfence();
    __syncthreads();
    if (threadIdx.x == 0) {
        volatile unsigned* vg = &g_gen;
        unsigned g = *vg;
        unsigned t = atomicAdd(&g_cnt, 1u);
        if (t == NCTA - 1) {
            atomicExch(&g_cnt, 0u);
            __threadfence();
            atomicAdd(&g_gen, 1u);
        } else {
            while (*vg == g) { }
        }
        __threadfence();
    }
    __syncthreads();
}

// Stage one 32-batch x 512-k fp16 chunk (32KB) by one 256-thread group.
__device__ __forceinline__ void stage_chunk(uint32_t smb, uint32_t bufo,
    const __half* __restrict__ A, int half_, int gtid)
{
    int b0 = half_ * 32;
    #pragma unroll
    for (int jj = 0; jj < 8; jj++) {
        int u = gtid + jj * 256;
        int b = u >> 6, seg = u & 63;
        const __half* s = A + (size_t)(b0 + b) * HID + seg * 8;
        cp16s(smb + bufo + (uint32_t)(b * 1040 + seg * 16), s);
    }
    CPCOMMIT();
}

// One chunk's MMA for this warp: 64k-slice, 2-term (Whi*A + Wlo*A).
__device__ __forceinline__ void chunk_mma(uint32_t smb, uint32_t bufo, int half_,
    const uint32_t wfm[2][4][4], uint32_t blane, int myks, float d[8][4])
{
    #pragma unroll
    for (int pair = 0; pair < 2; pair++) {
        #pragma unroll
        for (int kb = 0; kb < 4; kb++) {
            uint32_t addr = smb + bufo + (uint32_t)(pair * 16640) + blane
                          + (uint32_t)(myks * 128 + kb * 32);
            uint32_t b4[4];
            ldsm_x4(addr, b4);
            int nt = half_ * 4 + pair * 2;
            mma16816(d[nt],     wfm[0][kb], b4);
            mma16816(d[nt],     wfm[1][kb], b4);
            mma16816(d[nt + 1], wfm[0][kb], b4 + 2);
            mma16816(d[nt + 1], wfm[1][kb], b4 + 2);
        }
    }
}

__device__ __forceinline__ void store_partials(float* smf, uint32_t gbF,
    int myks, int lane, const float d[8][4])
{
    float* gb0 = smf + gbF + myks * 1088 + (lane >> 2) * 68 + 2 * (lane & 3);
    #pragma unroll
    for (int nt = 0; nt < 8; nt++) {
        *(float2*)(gb0 + nt * 8)          = make_float2(d[nt][0], d[nt][1]);
        *(float2*)(gb0 + 8 * 68 + nt * 8) = make_float2(d[nt][2], d[nt][3]);
    }
}

__global__ void convert_x(const float* __restrict__ x) {
    size_t i = (size_t)blockIdx.x * blockDim.x + threadIdx.x;   // float4 idx
    float4 v = reinterpret_cast<const float4*>(x)[i];
    __half2* p = reinterpret_cast<__half2*>(g_xh);
    p[2 * i]     = __floats2half2_rn(v.x, v.y);
    p[2 * i + 1] = __floats2half2_rn(v.z, v.w);
}

__global__ void __launch_bounds__(NTHR, 1) lstm_persistent(
    const float* __restrict__ Wxh,  // [2, 2048, 512]
    const float* __restrict__ Whh,  // [2, 2048, 512]
    const float* __restrict__ bxh,  // [2, 2048]
    const float* __restrict__ bhh,  // [2, 2048]
    float* __restrict__ out)        // [T*B*H] ++ hT[2,B,H] ++ cT[2,B,H]
{
    extern __shared__ float smf[];
    char* smc = (char*)smf;
    const uint32_t smb = (uint32_t)__cvta_generic_to_shared(smf);
    const int tid = threadIdx.x;
    const int bj  = blockIdx.x;

    const int wid = tid >> 5, lane = tid & 31, gtid = tid & 255;
    const bool isA = (wid < 8);                  // A = L1, B = L0'
    const int myks = isA ? wid : wid - 8;
    const int barid = isA ? 1 : 2;
    const uint32_t rb0 = isA ? BUFA(0) : BUFB(0);
    const uint32_t rb1 = isA ? BUFA(1) : BUFB(1);

    const uint32_t wloff = (uint32_t)(((lane & 7) + ((lane >> 3) & 1) * 8) * 1040
                                     + ((lane >> 4) & 1) * 16);
    const uint32_t blane = (uint32_t)((((lane >> 4) & 1) * 8 + (lane & 7)) * 1040
                                     + ((lane >> 3) & 1) * 16);

    uint32_t wf[2][2][4][4];   // [mat: in/rec][part: hi/lo][kb][4]
    const int glayer = isA ? 1 : 0;

    // ---- prologue: weights (x256) -> fp16 hi/lo tiles -> reg frags ----
    for (int l = 0; l < 2; l++) {
        for (int idx = tid; idx < 16384; idx += NTHR) {
            int m = idx >> 13, rem = idx & 8191, c = rem >> 9, k = rem & 511;
            const float* bp = m ? Whh : Wxh;
            float w = 256.0f * bp[((size_t)l * 2048 + (size_t)(c >> 2) * 512
                                 + bj * 4 + (c & 3)) * 512 + k];
            __half hi = __float2half(w);
            __half lo = __float2half(w - __half2float(hi));
            *(__half*)(smc + (m * 2 + 0) * 16640 + c * 1040 + k * 2) = hi;
            *(__half*)(smc + (m * 2 + 1) * 16640 + c * 1040 + k * 2) = lo;
        }
        __syncthreads();
        if (glayer == l) {
            #pragma unroll
            for (int m = 0; m < 2; m++)
                #pragma unroll
                for (int p = 0; p < 2; p++)
                    #pragma unroll
                    for (int kb = 0; kb < 4; kb++)
                        ldsm_x4(smb + (uint32_t)((m * 2 + p) * 16640)
                                + wloff + (uint32_t)((myks * 64 + kb * 16) * 2),
                                wf[m][p][kb]);
        }
        __syncthreads();
    }
    if (tid < 32) {
        int l = tid >> 4, j = tid & 15;
        int n = (j >> 2) * 512 + bj * 4 + (j & 3);
        smf[BSF + tid] = bxh[l * 2048 + n] + bhh[l * 2048 + n];
    }
    if (tid < 256) {      // zero h1 slot 2 (read at t=0)
        g_h1h[2][bj * 256 + tid] = __float2half(0.f);
    }

    const int ub = tid >> 2, ucc = tid & 3;       // update role (tid<256)
    const int col = bj * 4 + ucc;
    const int hidx = ub * HID + col;
    float c0r = 0.f, c1r = 0.f, h0last = 0.f, h1last = 0.f;
    float d[8][4];

    // ---- prologue B: L0(0) gates = x(0).Wx0 (h(-1)=0) ----
    #pragma unroll
    for (int nt = 0; nt < 8; nt++)
        d[nt][0] = d[nt][1] = d[nt][2] = d[nt][3] = 0.f;
    if (!isA) {
        stage_chunk(smb, rb0, g_xh, 0, gtid);
        stage_chunk(smb, rb1, g_xh, 1, gtid);
        CPWAIT(1); barg(2);
        chunk_mma(smb, rb0, 0, wf[0], blane, myks, d);
        CPWAIT(0); barg(2);
        chunk_mma(smb, rb1, 1, wf[0], blane, myks, d);
        barg(2);
        store_partials(smf, GB0F, myks, lane, d);
        // prestage x(1) for interval 0
        stage_chunk(smb, rb0, g_xh + (size_t)BSZ * HID, 0, gtid);
        stage_chunk(smb, rb1, g_xh + (size_t)BSZ * HID, 1, gtid);
    }
    __syncthreads();
    if (tid < 256) {
        float gate[4];
        #pragma unroll
        for (int g = 0; g < 4; g++) {
            const float* q = smf + GB0F + (g * 4 + ucc) * 68 + ub;
            float s = 0.f;
            #pragma unroll
            for (int sI = 0; sI < 8; sI++) s += q[sI * 1088];
            gate[g] = s * SCL + smf[BSF + g * 4 + ucc];
        }
        float ig = sigm(gate[0]), fg = sigm(gate[1]);
        float gg = tanhf(gate[2]), og = sigm(gate[3]);
        c0r = fg * c0r + ig * gg;
        h0last = og * tanhf(c0r);
        g_h0h[0][hidx] = __float2half(h0last);
    }
    grid_bar();

    // ---- main loop: interval t => L1(t) (group A) + L0(t+1) (group B) ----
    for (int t = 0; t < T_LEN; t++) {
        const int s_h0r = t % 3;              // h0(t) read slot
        const int s_h1r = (t + 2) % 3;        // h1(t-1) read slot
        const int s_h0w = (t + 1) % 3;        // h0(t+1) write slot
        const int s_h1w = t % 3;              // h1(t) write slot
        const size_t xo1 = (size_t)((t + 1 < T_LEN) ? t + 1 : T_LEN - 1) * (BSZ * HID);
        const size_t xo2 = (size_t)((t + 2 < T_LEN) ? t + 2 : T_LEN - 1) * (BSZ * HID);

        #pragma unroll
        for (int nt = 0; nt < 8; nt++)
            d[nt][0] = d[nt][1] = d[nt][2] = d[nt][3] = 0.f;

        // chunk sources: phases 0,1 = "input" mat; 2,3 = "recurrent" mat
        const __half* S0 = isA ? g_h0h[s_h0r] : (g_xh + xo1);
        const __half* S1 = isA ? g_h1h[s_h1r] : g_h0h[s_h0r];

        if (isA) {   // B's c0/c1 (x) were prestaged last interval
            stage_chunk(smb, rb0, S0, 0, gtid);
            stage_chunk(smb, rb1, S0, 1, gtid);
        }
        // phase 0
        CPWAIT(1); barg(barid);
        chunk_mma(smb, rb0, 0, wf[0], blane, myks, d);
        barg(barid);
        stage_chunk(smb, rb0, S1, 0, gtid);
        // phase 1
        CPWAIT(1); barg(barid);
        chunk_mma(smb, rb1, 1, wf[0], blane, myks, d);
        barg(barid);
        stage_chunk(smb, rb1, S1, 1, gtid);
        // phase 2
        CPWAIT(1); barg(barid);
        chunk_mma(smb, rb0, 0, wf[1], blane, myks, d);
        barg(barid);
        // phase 3
        CPWAIT(0); barg(barid);
        chunk_mma(smb, rb1, 1, wf[1], blane, myks, d);

        store_partials(smf, isA ? GB1F : GB0F, myks, lane, d);
        __syncthreads();

        if (!isA) {   // prestage x(t+2) -- overlaps group A's update
            stage_chunk(smb, rb0, g_xh + xo2, 0, gtid);
            stage_chunk(smb, rb1, g_xh + xo2, 1, gtid);
        }
        if (tid < 256) {
            float g1[4], g0[4];
            #pragma unroll
            for (int g = 0; g < 4; g++) {
                const float* q1 = smf + GB1F + (g * 4 + ucc) * 68 + ub;
                const float* q0 = smf + GB0F + (g * 4 + ucc) * 68 + ub;
                float s1 = 0.f, s0 = 0.f;
                #pragma unroll
                for (int sI = 0; sI < 8; sI++) { s1 += q1[sI * 1088];
                                                 s0 += q0[sI * 1088]; }
                g1[g] = s1 * SCL + smf[BSF + 16 + g * 4 + ucc];
                g0[g] = s0 * SCL + smf[BSF +      g * 4 + ucc];
            }
            {
                float ig = sigm(g1[0]), fg = sigm(g1[1]);
                float gg = tanhf(g1[2]), og = sigm(g1[3]);
                c1r = fg * c1r + ig * gg;
                h1last = og * tanhf(c1r);
                g_h1h[s_h1w][hidx] = __float2half(h1last);
                out[(size_t)t * (BSZ * HID) + hidx] = h1last;
            }
            if (t < T_LEN - 1) {
                float ig = sigm(g0[0]), fg = sigm(g0[1]);
                float gg = tanhf(g0[2]), og = sigm(g0[3]);
                c0r = fg * c0r + ig * gg;
                h0last = og * tanhf(c0r);
                g_h0h[s_h0w][hidx] = __float2half(h0last);
            }
        }
        grid_bar();
    }
    CPWAIT(0);

    // ---- epilogue: (hT, cT) straight from registers ----
    if (tid < 256) {
        const size_t OFF = (size_t)T_LEN * BSZ * HID;
        out[OFF +         hidx] = h0last;
        out[OFF + 32768 + hidx] = h1last;
        out[OFF + 65536 + hidx] = c0r;
        out[OFF + 98304 + hidx] = c1r;
    }
}

extern "C" void kernel_launch(void* const* d_in, const int* in_sizes, int n_in,
                              void* d_out, int out_size) {
    const float* x   = (const float*)d_in[0];
    const float* Wxh = (const float*)d_in[1];
    const float* Whh = (const float*)d_in[2];
    const float* bxh = (const float*)d_in[3];
    const float* bhh = (const float*)d_in[4];
    float* out = (float*)d_out;

    convert_x<<<(T_LEN * BSZ * HID / 4) / 256, 256>>>(x);

    cudaFuncSetAttribute(lstm_persistent,
                         cudaFuncAttributeMaxDynamicSharedMemorySize, SMEM_BYTES);
    lstm_persistent<<<NCTA, NTHR, SMEM_BYTES>>>(Wxh, Whh, bxh, bhh, out);
}